// round 15
// baseline (speedup 1.0000x reference)
#include <cuda_runtime.h>
#include <cuda_fp16.h>
#include <math.h>

// Problem-fixed sizes (from reference setup_inputs)
#define NMAX 50000
#define EMAX 600000
#define TOTMAX (EMAX + NMAX)
#define BGRID 592            // 148 SMs * 4 — co-resident by construction
#define BTHREADS 256
#define CHUNK 85             // ceil(50000 / 592)

// Scratch (static device arrays; no allocation allowed; zero-initialized)
__device__ __half g_h[NMAX * 128];     // projected features [N, H*D] (fp16)
__device__ float g_asrc[NMAX * 4];     // per-node src attention half (fp32)
__device__ float g_adst[NMAX * 4];     // per-node dst attention half (fp32)
__device__ int2  g_edges[TOTMAX];      // decoded (src, dst) incl. self-loops
__device__ int   g_cnt[NMAX];          // in-degree histogram (self-cleaning)
__device__ int   g_off[NMAX + 1];      // CSR offsets (exclusive scan)
__device__ int   g_pos[NMAX];          // scatter cursors
__device__ int   g_csr[TOTMAX];        // CSR: src ids grouped by dst
__device__ int   g_bsum[BGRID];        // per-block chunk totals
__device__ unsigned g_bar;             // device-wide barrier (reset by agg)
__device__ int   g_gemm_done;          // gemm completed-block counter
__device__ int   g_agg_done;           // agg completed-block counter

// ---------------------------------------------------------------------------
// packed fp32x2 FMA (sm_100+; ptxas never emits FFMA2 from C++)
// ---------------------------------------------------------------------------
__device__ __forceinline__ void fma2(unsigned long long& acc,
                                     unsigned long long a,
                                     unsigned long long b) {
    asm("fma.rn.f32x2 %0, %1, %2, %3;" : "=l"(acc) : "l"(a), "l"(b), "l"(acc));
}
__device__ __forceinline__ unsigned long long pack2(float v) {
    unsigned long long r;
    asm("mov.b64 %0, {%1, %1};" : "=l"(r) : "f"(v));
    return r;
}
__device__ __forceinline__ void unpack2(unsigned long long v, float& lo, float& hi) {
    asm("mov.b64 {%0, %1}, %2;" : "=f"(lo), "=f"(hi) : "l"(v));
}

// fast tanh: clamped exp identity; rel err ~1e-6
__device__ __forceinline__ float fast_tanh(float x) {
    x = fminf(fmaxf(x, -9.0f), 9.0f);
    float t = __expf(2.0f * x);
    return (t - 1.0f) * __fdividef(1.0f, t + 1.0f);
}

// ---------------------------------------------------------------------------
// device-wide barrier (blocks co-resident by construction)
// ---------------------------------------------------------------------------
__device__ __forceinline__ void grid_barrier(unsigned target) {
    __syncthreads();
    if (threadIdx.x == 0) {
        __threadfence();
        atomicAdd(&g_bar, 1u);
        while (atomicAdd(&g_bar, 0u) < target) { }
    }
    __syncthreads();
}

// ---------------------------------------------------------------------------
// Shared GEMM epilogue: attention partials + fp16 pack + store for one row
// ---------------------------------------------------------------------------
__device__ __forceinline__ void gemm_epilogue_row(
    int row, int N, int t, int head, int c0,
    const float acc[8], const float avs[8], const float avd[8]) {
    float ps = 0.0f, pd = 0.0f;
#pragma unroll
    for (int j = 0; j < 8; j++) {
        ps += acc[j] * avs[j];
        pd += acc[j] * avd[j];
    }
    ps += __shfl_xor_sync(0xFFFFFFFFu, ps, 1);
    ps += __shfl_xor_sync(0xFFFFFFFFu, ps, 2);
    pd += __shfl_xor_sync(0xFFFFFFFFu, pd, 1);
    pd += __shfl_xor_sync(0xFFFFFFFFu, pd, 2);

    if (row < N) {
        __half2 p0 = __floats2half2_rn(acc[0], acc[1]);
        __half2 p1 = __floats2half2_rn(acc[2], acc[3]);
        __half2 p2 = __floats2half2_rn(acc[4], acc[5]);
        __half2 p3 = __floats2half2_rn(acc[6], acc[7]);
        uint4 pk;
        pk.x = *(unsigned*)&p0;
        pk.y = *(unsigned*)&p1;
        pk.z = *(unsigned*)&p2;
        pk.w = *(unsigned*)&p3;
        *(uint4*)&g_h[(long long)row * 128 + c0] = pk;
        if ((t & 3) == 0) {
            g_asrc[row * 4 + head] = ps;
            g_adst[row * 4 + head] = pd;
        }
    }
}

// release-signal: all block stores visible, then count this block done
__device__ __forceinline__ void gemm_signal_done() {
    __threadfence();
    __syncthreads();
    if (threadIdx.x == 0) atomicAdd(&g_gemm_done, 1);
}

// ---------------------------------------------------------------------------
// K1: smem-staged GEMM. 256 threads, 64-row tile, 4 rows/thread, W (64KB)
// in dynamic smem. __launch_bounds__(256,3): regs capped so 3 blocks/SM
// co-reside (24 warps, ~37% occ) — fixes the regs=132/occ=12% starvation.
// ---------------------------------------------------------------------------
__global__ void __launch_bounds__(256, 3) gemm_smem_kernel(
    const float* __restrict__ x, const float* __restrict__ W,
    const float* __restrict__ att_s, const float* __restrict__ att_d, int N) {

    extern __shared__ float sW[];

    int t  = threadIdx.x;
    {
        const float4* Wv = (const float4*)W;
        float4* sWv = (float4*)sW;
#pragma unroll
        for (int i = 0; i < 16; i++)
            sWv[t + i * 256] = Wv[t + i * 256];
    }
    __syncthreads();

    int cg = t & 15;
    int rg = t >> 4;                      // 16 row groups
    int c0 = cg * 8;
    int row0 = blockIdx.x * 64 + rg * 4;  // 4 rows per thread

    unsigned long long acc2[4][4];
#pragma unroll
    for (int r = 0; r < 4; r++)
#pragma unroll
        for (int j = 0; j < 4; j++) acc2[r][j] = 0ULL;

    int rrow[4];
#pragma unroll
    for (int r = 0; r < 4; r++) {
        int rr = row0 + r;
        rrow[r] = rr < N ? rr : (N - 1);
    }

    for (int k = 0; k < 128; k += 4) {
        float4 xv[4];
#pragma unroll
        for (int r = 0; r < 4; r++)
            xv[r] = *(const float4*)&x[(long long)rrow[r] * 128 + k];
#pragma unroll
        for (int kk = 0; kk < 4; kk++) {
            ulonglong2 wA = *(const ulonglong2*)&sW[(k + kk) * 128 + c0];
            ulonglong2 wB = *(const ulonglong2*)&sW[(k + kk) * 128 + c0 + 4];
#pragma unroll
            for (int r = 0; r < 4; r++) {
                float xs = (kk == 0) ? xv[r].x : (kk == 1) ? xv[r].y
                          : (kk == 2) ? xv[r].z : xv[r].w;
                unsigned long long xs2 = pack2(xs);
                fma2(acc2[r][0], xs2, wA.x);
                fma2(acc2[r][1], xs2, wA.y);
                fma2(acc2[r][2], xs2, wB.x);
                fma2(acc2[r][3], xs2, wB.y);
            }
        }
    }

    float4 as0 = *(const float4*)&att_s[c0];
    float4 as1 = *(const float4*)&att_s[c0 + 4];
    float4 ad0 = *(const float4*)&att_d[c0];
    float4 ad1 = *(const float4*)&att_d[c0 + 4];
    float avs[8] = {as0.x, as0.y, as0.z, as0.w, as1.x, as1.y, as1.z, as1.w};
    float avd[8] = {ad0.x, ad0.y, ad0.z, ad0.w, ad1.x, ad1.y, ad1.z, ad1.w};
    int head = c0 >> 5;

#pragma unroll
    for (int r = 0; r < 4; r++) {
        float acc[8];
#pragma unroll
        for (int j = 0; j < 4; j++)
            unpack2(acc2[r][j], acc[2 * j], acc[2 * j + 1]);
        gemm_epilogue_row(row0 + r, N, t, head, c0, acc, avs, avd);
    }
    gemm_signal_done();
}

// ---------------------------------------------------------------------------
// K1 (fallback): register-blocked gemm if smem opt-in failed
// ---------------------------------------------------------------------------
__global__ void __launch_bounds__(128) gemm_kernel(
    const float* __restrict__ x, const float* __restrict__ W,
    const float* __restrict__ att_s, const float* __restrict__ att_d, int N) {

    int t  = threadIdx.x;
    int cg = t & 15;
    int rg = t >> 4;
    int c0 = cg * 8;
    int row0 = blockIdx.x * 32 + rg * 4;

    unsigned long long acc2[4][4];
#pragma unroll
    for (int r = 0; r < 4; r++)
#pragma unroll
        for (int j = 0; j < 4; j++) acc2[r][j] = 0ULL;

    int rrow[4];
#pragma unroll
    for (int r = 0; r < 4; r++) {
        int rr = row0 + r;
        rrow[r] = rr < N ? rr : (N - 1);
    }

    for (int k = 0; k < 128; k += 4) {
        float4 xv[4];
#pragma unroll
        for (int r = 0; r < 4; r++)
            xv[r] = *(const float4*)&x[(long long)rrow[r] * 128 + k];
#pragma unroll
        for (int kk = 0; kk < 4; kk++) {
            ulonglong2 wA = *(const ulonglong2*)&W[(k + kk) * 128 + c0];
            ulonglong2 wB = *(const ulonglong2*)&W[(k + kk) * 128 + c0 + 4];
#pragma unroll
            for (int r = 0; r < 4; r++) {
                float xs = (kk == 0) ? xv[r].x : (kk == 1) ? xv[r].y
                          : (kk == 2) ? xv[r].z : xv[r].w;
                unsigned long long xs2 = pack2(xs);
                fma2(acc2[r][0], xs2, wA.x);
                fma2(acc2[r][1], xs2, wA.y);
                fma2(acc2[r][2], xs2, wB.x);
                fma2(acc2[r][3], xs2, wB.y);
            }
        }
    }

    float4 as0 = *(const float4*)&att_s[c0];
    float4 as1 = *(const float4*)&att_s[c0 + 4];
    float4 ad0 = *(const float4*)&att_d[c0];
    float4 ad1 = *(const float4*)&att_d[c0 + 4];
    float avs[8] = {as0.x, as0.y, as0.z, as0.w, as1.x, as1.y, as1.z, as1.w};
    float avd[8] = {ad0.x, ad0.y, ad0.z, ad0.w, ad1.x, ad1.y, ad1.z, ad1.w};
    int head = c0 >> 5;

#pragma unroll
    for (int r = 0; r < 4; r++) {
        float acc[8];
#pragma unroll
        for (int j = 0; j < 4; j++)
            unpack2(acc2[r][j], acc[2 * j], acc[2 * j + 1]);
        gemm_epilogue_row(row0 + r, N, t, head, c0, acc, avs, avd);
    }
    gemm_signal_done();
}

// ---------------------------------------------------------------------------
// K2 (fused, self-cleaning): hist -> scan (zeroes g_cnt) -> offsets -> scatter.
// ---------------------------------------------------------------------------
__global__ void __launch_bounds__(BTHREADS) build_kernel(
    const void* __restrict__ ei, int E, int N) {

    __shared__ int sh_is64;
    int t = threadIdx.x, b = blockIdx.x;
    int gtid = b * BTHREADS + t;
    const int nthr = BGRID * BTHREADS;
    int tot = E + N;

    if (t == 0) {
        const int* e32 = (const int*)ei;
        int is64 = 1;
        if (e32[1] != 0) is64 = 0;
        if (e32[3] != 0) is64 = 0;
        if (e32[5] != 0) is64 = 0;
        if (e32[7] != 0) is64 = 0;
        sh_is64 = is64;
    }
    __syncthreads();
    int is64 = sh_is64;

    // ---- Phase 1: decode + histogram ----
    for (int i = gtid; i < tot; i += nthr) {
        int s, d;
        if (i < E) {
            if (is64) {
                const long long* p = (const long long*)ei;
                s = (int)p[i];
                d = (int)p[E + i];
            } else {
                const int* p = (const int*)ei;
                s = p[i];
                d = p[E + i];
            }
        } else {
            s = d = i - E;
        }
        g_edges[i] = make_int2(s, d);
        atomicAdd(&g_cnt[d], 1);
    }
    grid_barrier(BGRID);

    // ---- Phase 2: per-block chunk scan (reads then zeroes g_cnt) ----
    __shared__ int sh_scan[BTHREADS];
    __shared__ int sh_red[BTHREADS];
    int chunk0 = b * CHUNK;
    int v = 0;
    int idx = chunk0 + t;
    if (t < CHUNK && idx < N) {
        v = g_cnt[idx];
        g_cnt[idx] = 0;              // self-clean for next replay
    }
    int lane = t & 31, wid = t >> 5;
    int x = v;
#pragma unroll
    for (int o = 1; o < 32; o <<= 1) {
        int y = __shfl_up_sync(0xFFFFFFFFu, x, o);
        if (lane >= o) x += y;
    }
    if (lane == 31) sh_scan[wid] = x;
    __syncthreads();
    if (wid == 0 && lane < 8) {
        int ws = sh_scan[lane];
#pragma unroll
        for (int o = 1; o < 8; o <<= 1) {
            int y = __shfl_up_sync(0xFFu, ws, o);
            if (lane >= o) ws += y;
        }
        sh_scan[lane] = ws;
    }
    __syncthreads();
    int warp_excl = (wid == 0) ? 0 : sh_scan[wid - 1];
    int excl = warp_excl + x - v;
    int btotal = sh_scan[7];
    if (t == 0) g_bsum[b] = btotal;
    grid_barrier(2u * BGRID);

    // ---- Phase 3: every block prefixes the BGRID totals, writes offsets ----
    {
        int before = 0, all = 0;
        for (int j = t; j < BGRID; j += BTHREADS) {
            int bv = g_bsum[j];
            all += bv;
            if (j < b) before += bv;
        }
        sh_scan[t] = before;
        sh_red[t]  = all;
        __syncthreads();
        for (int o = BTHREADS / 2; o > 0; o >>= 1) {
            if (t < o) {
                sh_scan[t] += sh_scan[t + o];
                sh_red[t]  += sh_red[t + o];
            }
            __syncthreads();
        }
        int base = sh_scan[0];
        int grand = sh_red[0];
        if (t < CHUNK && idx < N) {
            int o2 = base + excl;
            g_off[idx] = o2;
            g_pos[idx] = o2;
        }
        if (b == 0 && t == 0) g_off[N] = grand;
    }
    grid_barrier(3u * BGRID);

    // ---- Phase 4: scatter ----
    for (int i = gtid; i < tot; i += nthr) {
        int2 e = g_edges[i];
        int pos = atomicAdd(&g_pos[e.y], 1);
        g_csr[pos] = e.x;
    }
}

// ---------------------------------------------------------------------------
// K3: aggregation. Spins until gemm signals done; one warp per dst node;
// simple prefetch loop, fp16 h gather, fast-tanh. Last block resets state.
// ---------------------------------------------------------------------------
__global__ void __launch_bounds__(128) agg_kernel(float* __restrict__ out,
                                                  const float* __restrict__ bias,
                                                  int N, int n_gemm_blocks,
                                                  int n_agg_blocks) {
    if (threadIdx.x == 0) {
        while (atomicAdd(&g_gemm_done, 0) < n_gemm_blocks) { }
        __threadfence();
    }
    __syncthreads();

    int gw   = (blockIdx.x * blockDim.x + threadIdx.x) >> 5;
    int lane = threadIdx.x & 31;

    if (gw < N) {
        int d    = gw;
        int head = lane >> 3;

        int beg = __ldg(&g_off[d]);
        int end = __ldg(&g_off[d + 1]);

        float adv = g_adst[d * 4 + head];
        float den = 0.0f;
        float ax = 0.0f, ay = 0.0f, az = 0.0f, aw = 0.0f;

        int s = (beg < end) ? __ldg(&g_csr[beg]) : 0;
        for (int j = beg; j < end; j++) {
            float as = __ldg(&g_asrc[s * 4 + head]);
            uint2 raw = *(const uint2*)&g_h[(long long)s * 128 + lane * 4];
            int s_next = (j + 1 < end) ? __ldg(&g_csr[j + 1]) : 0;

            float l = as + adv;
            l = fmaxf(l, 0.2f * l);
            float e = __expf(l);
            den += e;

            __half2 h01 = *(__half2*)&raw.x;
            __half2 h23 = *(__half2*)&raw.y;
            float2 f01 = __half22float2(h01);
            float2 f23 = __half22float2(h23);
            ax += f01.x * e;
            ay += f01.y * e;
            az += f23.x * e;
            aw += f23.y * e;
            s = s_next;
        }

        float inv = __fdividef(1.0f, den);
        float4 bv = *(const float4*)&bias[lane * 4];
        float4 ov;
        ov.x = fast_tanh(ax * inv + bv.x);
        ov.y = fast_tanh(ay * inv + bv.y);
        ov.z = fast_tanh(az * inv + bv.z);
        ov.w = fast_tanh(aw * inv + bv.w);
        *(float4*)&out[(long long)d * 128 + lane * 4] = ov;
    }

    __syncthreads();
    if (threadIdx.x == 0) {
        int c = atomicAdd(&g_agg_done, 1);
        if (c == n_agg_blocks - 1) {
            g_agg_done = 0;
            g_gemm_done = 0;
            g_bar = 0u;
            __threadfence();
        }
    }
}

// ---------------------------------------------------------------------------
// Host-side one-time setup: side stream/events + smem opt-in for gemm.
// ---------------------------------------------------------------------------
#define GEMM_SMEM_BYTES (128 * 128 * sizeof(float))
static cudaStream_t g_s1 = 0;
static cudaEvent_t  g_e0 = 0, g_e1 = 0;
static bool g_forked = false;
static bool g_smem_ok = false;
static struct SideStreamInit {
    SideStreamInit() {
        bool ok = true;
        ok &= (cudaStreamCreateWithFlags(&g_s1, cudaStreamNonBlocking) == cudaSuccess);
        ok &= (cudaEventCreateWithFlags(&g_e0, cudaEventDisableTiming) == cudaSuccess);
        ok &= (cudaEventCreateWithFlags(&g_e1, cudaEventDisableTiming) == cudaSuccess);
        g_forked = ok;
        g_smem_ok = (cudaFuncSetAttribute(gemm_smem_kernel,
                        cudaFuncAttributeMaxDynamicSharedMemorySize,
                        (int)GEMM_SMEM_BYTES) == cudaSuccess);
    }
} g_side_stream_init;

static inline int gemm_blocks(int N) {
    return g_smem_ok ? (N + 63) / 64 : (N + 31) / 32;
}
static inline void launch_gemm(const float* x, const float* W,
                               const float* att_s, const float* att_d,
                               int N, cudaStream_t st) {
    if (g_smem_ok)
        gemm_smem_kernel<<<(N + 63) / 64, 256, GEMM_SMEM_BYTES, st>>>(
            x, W, att_s, att_d, N);
    else
        gemm_kernel<<<(N + 31) / 32, 128, 0, st>>>(x, W, att_s, att_d, N);
}

// ---------------------------------------------------------------------------
extern "C" void kernel_launch(void* const* d_in, const int* in_sizes, int n_in,
                              void* d_out, int out_size) {
    const float* x     = (const float*)d_in[0];
    const void*  ei    = d_in[1];
    const float* W     = (const float*)d_in[2];
    const float* att_s = (const float*)d_in[3];
    const float* att_d = (const float*)d_in[4];
    const float* bias  = (const float*)d_in[5];
    float* out = (float*)d_out;

    int N = in_sizes[0] / 128;
    int E = in_sizes[1] / 2;
    int ngemm = gemm_blocks(N);
    int nagg  = (N * 32 + 127) / 128;

    if (g_forked) {
        cudaEventRecord(g_e0, 0);
        cudaStreamWaitEvent(g_s1, g_e0, 0);
        launch_gemm(x, W, att_s, att_d, N, g_s1);
        cudaEventRecord(g_e1, g_s1);

        build_kernel<<<BGRID, BTHREADS>>>(ei, E, N);
        agg_kernel<<<nagg, 128>>>(out, bias, N, ngemm, nagg);

        cudaStreamWaitEvent(0, g_e1, 0);   // closes capture; off critical path
    } else {
        launch_gemm(x, W, att_s, att_d, N, 0);
        build_kernel<<<BGRID, BTHREADS>>>(ei, E, N);
        agg_kernel<<<nagg, 128>>>(out, bias, N, ngemm, nagg);
    }
}

// round 17
// speedup vs baseline: 1.4047x; 1.4047x over previous
#include <cuda_runtime.h>
#include <cuda_fp16.h>
#include <math.h>

// Problem-fixed sizes (from reference setup_inputs)
#define NMAX 50000
#define EMAX 600000
#define TOTMAX (EMAX + NMAX)
#define BGRID 592            // 148 SMs * 4 — co-resident by construction
#define BTHREADS 256
#define CHUNK 85             // ceil(50000 / 592)

// Scratch (static device arrays; no allocation allowed; zero-initialized)
__device__ __half g_h[NMAX * 128];     // projected features [N, H*D] (fp16)
__device__ float g_asrc[NMAX * 4];     // per-node src attention half (fp32)
__device__ float g_adst[NMAX * 4];     // per-node dst attention half (fp32)
__device__ int2  g_edges[TOTMAX];      // decoded (src, dst) incl. self-loops
__device__ int   g_cnt[NMAX];          // in-degree histogram (self-cleaning)
__device__ int   g_off[NMAX + 1];      // CSR offsets (exclusive scan)
__device__ int   g_pos[NMAX];          // scatter cursors
__device__ int   g_csr[TOTMAX];        // CSR: src ids grouped by dst
__device__ int   g_bsum[BGRID];        // per-block chunk totals
__device__ uint2 g_Wfrag[8 * 16 * 32]; // W as fp16 m16n8k16 B-fragments
__device__ unsigned g_bar;             // device-wide barrier (reset by agg)
__device__ int   g_gemm_done;          // gemm completed-block counter
__device__ int   g_agg_done;           // agg completed-block counter

// fast tanh: clamped exp identity; rel err ~1e-6
__device__ __forceinline__ float fast_tanh(float x) {
    x = fminf(fmaxf(x, -9.0f), 9.0f);
    float t = __expf(2.0f * x);
    return (t - 1.0f) * __fdividef(1.0f, t + 1.0f);
}

// m16n8k16 fp16 MMA, fp32 accumulate (HMMA tensor-core path)
__device__ __forceinline__ void mma16816(float c[4], const unsigned a[4],
                                         const uint2 b) {
    asm volatile(
        "mma.sync.aligned.m16n8k16.row.col.f32.f16.f16.f32 "
        "{%0,%1,%2,%3}, {%4,%5,%6,%7}, {%8,%9}, {%0,%1,%2,%3};"
        : "+f"(c[0]), "+f"(c[1]), "+f"(c[2]), "+f"(c[3])
        : "r"(a[0]), "r"(a[1]), "r"(a[2]), "r"(a[3]), "r"(b.x), "r"(b.y));
}

// ---------------------------------------------------------------------------
// device-wide barrier (blocks co-resident by construction)
// ---------------------------------------------------------------------------
__device__ __forceinline__ void grid_barrier(unsigned target) {
    __syncthreads();
    if (threadIdx.x == 0) {
        __threadfence();
        atomicAdd(&g_bar, 1u);
        while (atomicAdd(&g_bar, 0u) < target) { }
    }
    __syncthreads();
}

__device__ __forceinline__ void gemm_signal_done() {
    __threadfence();
    __syncthreads();
    if (threadIdx.x == 0) atomicAdd(&g_gemm_done, 1);
}

// ---------------------------------------------------------------------------
// K0 (side stream): pack W (fp32) into fp16 m16n8k16 B-fragments.
// B col-major 16x8: thread holds B[tg*2+{0,1}][g] and B[tg*2+8+{0,1}][g],
// g = lane>>2, tg = lane&3. One uint2 per (kstep, ntile, lane).
// ---------------------------------------------------------------------------
__global__ void __launch_bounds__(128) wconv_kernel(const float* __restrict__ W) {
    int idx = blockIdx.x * blockDim.x + threadIdx.x;
    if (idx >= 8 * 16 * 32) return;
    int ks   = idx >> 9;
    int nt   = (idx >> 5) & 15;
    int lane = idx & 31;
    int tg = lane & 3;
    int n  = nt * 8 + (lane >> 2);
    int k0 = ks * 16 + tg * 2;
    float f00 = W[(k0 + 0) * 128 + n];
    float f01 = W[(k0 + 1) * 128 + n];
    float f10 = W[(k0 + 8) * 128 + n];
    float f11 = W[(k0 + 9) * 128 + n];
    __half2 u0 = __floats2half2_rn(f00, f01);
    __half2 u1 = __floats2half2_rn(f10, f11);
    g_Wfrag[idx] = make_uint2(*(unsigned*)&u0, *(unsigned*)&u1);
}

// ---------------------------------------------------------------------------
// K1: tensor-core GEMM. 4 warps/block, warp = 16-row x 128-col strip.
// A frags from fp32 x (register convert), B frags from g_Wfrag (L1-resident).
// fp32 accum -> per-head attention dots (exact) + fp16 h store.
// ---------------------------------------------------------------------------
__global__ void __launch_bounds__(128) gemm_mma_kernel(
    const float* __restrict__ x,
    const float* __restrict__ att_s, const float* __restrict__ att_d, int N) {

    int warp = threadIdx.x >> 5;
    int lane = threadIdx.x & 31;
    int g  = lane >> 2;
    int tg = lane & 3;
    int row0 = blockIdx.x * 64 + warp * 16;
    int rA = row0 + g;
    int rB = row0 + g + 8;
    long long rAc = (rA < N) ? rA : (N - 1);
    long long rBc = (rB < N) ? rB : (N - 1);
    const float* xA = x + rAc * 128 + tg * 2;
    const float* xB = x + rBc * 128 + tg * 2;

    float c[16][4];
#pragma unroll
    for (int nt = 0; nt < 16; nt++) {
        c[nt][0] = c[nt][1] = c[nt][2] = c[nt][3] = 0.0f;
    }

#pragma unroll
    for (int ks = 0; ks < 8; ks++) {
        int k = ks * 16;
        float2 x0 = *(const float2*)(xA + k);
        float2 x1 = *(const float2*)(xB + k);
        float2 x2 = *(const float2*)(xA + k + 8);
        float2 x3 = *(const float2*)(xB + k + 8);
        __half2 h0 = __floats2half2_rn(x0.x, x0.y);
        __half2 h1 = __floats2half2_rn(x1.x, x1.y);
        __half2 h2 = __floats2half2_rn(x2.x, x2.y);
        __half2 h3 = __floats2half2_rn(x3.x, x3.y);
        unsigned a[4] = {*(unsigned*)&h0, *(unsigned*)&h1,
                         *(unsigned*)&h2, *(unsigned*)&h3};
        const uint2* wf = &g_Wfrag[ks * 16 * 32 + lane];
#pragma unroll
        for (int nt = 0; nt < 16; nt++) {
            uint2 b = __ldg(&wf[nt * 32]);
            mma16816(c[nt], a, b);
        }
    }

    // per-head attention dots (rows rA, rB)
    float ps[2][4], pd[2][4];
#pragma unroll
    for (int r = 0; r < 2; r++)
#pragma unroll
        for (int h = 0; h < 4; h++) { ps[r][h] = 0.0f; pd[r][h] = 0.0f; }

#pragma unroll
    for (int nt = 0; nt < 16; nt++) {
        int h = nt >> 2;
#pragma unroll
        for (int i = 0; i < 2; i++) {
            int col = nt * 8 + tg * 2 + i;
            float s  = __ldg(&att_s[col]);
            float dd = __ldg(&att_d[col]);
            ps[0][h] += c[nt][i] * s;
            pd[0][h] += c[nt][i] * dd;
            ps[1][h] += c[nt][2 + i] * s;
            pd[1][h] += c[nt][2 + i] * dd;
        }
    }
    // reduce over the quad (lanes tg=0..3 share rows)
#pragma unroll
    for (int r = 0; r < 2; r++)
#pragma unroll
        for (int h = 0; h < 4; h++) {
            float v = ps[r][h];
            v += __shfl_xor_sync(0xFFFFFFFFu, v, 1);
            v += __shfl_xor_sync(0xFFFFFFFFu, v, 2);
            ps[r][h] = v;
            float w = pd[r][h];
            w += __shfl_xor_sync(0xFFFFFFFFu, w, 1);
            w += __shfl_xor_sync(0xFFFFFFFFu, w, 2);
            pd[r][h] = w;
        }

    if (rA < N) {
#pragma unroll
        for (int nt = 0; nt < 16; nt++) {
            __half2 hh = __floats2half2_rn(c[nt][0], c[nt][1]);
            *(__half2*)&g_h[(long long)rA * 128 + nt * 8 + tg * 2] = hh;
        }
        if (tg == 0) {
#pragma unroll
            for (int h = 0; h < 4; h++) {
                g_asrc[rA * 4 + h] = ps[0][h];
                g_adst[rA * 4 + h] = pd[0][h];
            }
        }
    }
    if (rB < N) {
#pragma unroll
        for (int nt = 0; nt < 16; nt++) {
            __half2 hh = __floats2half2_rn(c[nt][2], c[nt][3]);
            *(__half2*)&g_h[(long long)rB * 128 + nt * 8 + tg * 2] = hh;
        }
        if (tg == 0) {
#pragma unroll
            for (int h = 0; h < 4; h++) {
                g_asrc[rB * 4 + h] = ps[1][h];
                g_adst[rB * 4 + h] = pd[1][h];
            }
        }
    }
    gemm_signal_done();
}

// ---------------------------------------------------------------------------
// K2 (fused, self-cleaning): hist -> scan (zeroes g_cnt) -> offsets -> scatter.
// ---------------------------------------------------------------------------
__global__ void __launch_bounds__(BTHREADS) build_kernel(
    const void* __restrict__ ei, int E, int N) {

    __shared__ int sh_is64;
    int t = threadIdx.x, b = blockIdx.x;
    int gtid = b * BTHREADS + t;
    const int nthr = BGRID * BTHREADS;
    int tot = E + N;

    if (t == 0) {
        const int* e32 = (const int*)ei;
        int is64 = 1;
        if (e32[1] != 0) is64 = 0;
        if (e32[3] != 0) is64 = 0;
        if (e32[5] != 0) is64 = 0;
        if (e32[7] != 0) is64 = 0;
        sh_is64 = is64;
    }
    __syncthreads();
    int is64 = sh_is64;

    // ---- Phase 1: decode + histogram ----
    for (int i = gtid; i < tot; i += nthr) {
        int s, d;
        if (i < E) {
            if (is64) {
                const long long* p = (const long long*)ei;
                s = (int)p[i];
                d = (int)p[E + i];
            } else {
                const int* p = (const int*)ei;
                s = p[i];
                d = p[E + i];
            }
        } else {
            s = d = i - E;
        }
        g_edges[i] = make_int2(s, d);
        atomicAdd(&g_cnt[d], 1);
    }
    grid_barrier(BGRID);

    // ---- Phase 2: per-block chunk scan (reads then zeroes g_cnt) ----
    __shared__ int sh_scan[BTHREADS];
    __shared__ int sh_red[BTHREADS];
    int chunk0 = b * CHUNK;
    int v = 0;
    int idx = chunk0 + t;
    if (t < CHUNK && idx < N) {
        v = g_cnt[idx];
        g_cnt[idx] = 0;              // self-clean for next replay
    }
    int lane = t & 31, wid = t >> 5;
    int x = v;
#pragma unroll
    for (int o = 1; o < 32; o <<= 1) {
        int y = __shfl_up_sync(0xFFFFFFFFu, x, o);
        if (lane >= o) x += y;
    }
    if (lane == 31) sh_scan[wid] = x;
    __syncthreads();
    if (wid == 0 && lane < 8) {
        int ws = sh_scan[lane];
#pragma unroll
        for (int o = 1; o < 8; o <<= 1) {
            int y = __shfl_up_sync(0xFFu, ws, o);
            if (lane >= o) ws += y;
        }
        sh_scan[lane] = ws;
    }
    __syncthreads();
    int warp_excl = (wid == 0) ? 0 : sh_scan[wid - 1];
    int excl = warp_excl + x - v;
    int btotal = sh_scan[7];
    if (t == 0) g_bsum[b] = btotal;
    grid_barrier(2u * BGRID);

    // ---- Phase 3: every block prefixes the BGRID totals, writes offsets ----
    {
        int before = 0, all = 0;
        for (int j = t; j < BGRID; j += BTHREADS) {
            int bv = g_bsum[j];
            all += bv;
            if (j < b) before += bv;
        }
        sh_scan[t] = before;
        sh_red[t]  = all;
        __syncthreads();
        for (int o = BTHREADS / 2; o > 0; o >>= 1) {
            if (t < o) {
                sh_scan[t] += sh_scan[t + o];
                sh_red[t]  += sh_red[t + o];
            }
            __syncthreads();
        }
        int base = sh_scan[0];
        int grand = sh_red[0];
        if (t < CHUNK && idx < N) {
            int o2 = base + excl;
            g_off[idx] = o2;
            g_pos[idx] = o2;
        }
        if (b == 0 && t == 0) g_off[N] = grand;
    }
    grid_barrier(3u * BGRID);

    // ---- Phase 4: scatter ----
    for (int i = gtid; i < tot; i += nthr) {
        int2 e = g_edges[i];
        int pos = atomicAdd(&g_pos[e.y], 1);
        g_csr[pos] = e.x;
    }
}

// ---------------------------------------------------------------------------
// K3: aggregation. Spins until gemm signals done; one warp per dst node;
// simple prefetch loop, fp16 h gather, fast-tanh. Last block resets state.
// ---------------------------------------------------------------------------
__global__ void __launch_bounds__(128) agg_kernel(float* __restrict__ out,
                                                  const float* __restrict__ bias,
                                                  int N, int n_gemm_blocks,
                                                  int n_agg_blocks) {
    if (threadIdx.x == 0) {
        while (atomicAdd(&g_gemm_done, 0) < n_gemm_blocks) { }
        __threadfence();
    }
    __syncthreads();

    int gw   = (blockIdx.x * blockDim.x + threadIdx.x) >> 5;
    int lane = threadIdx.x & 31;

    if (gw < N) {
        int d    = gw;
        int head = lane >> 3;

        int beg = __ldg(&g_off[d]);
        int end = __ldg(&g_off[d + 1]);

        float adv = g_adst[d * 4 + head];
        float den = 0.0f;
        float ax = 0.0f, ay = 0.0f, az = 0.0f, aw = 0.0f;

        int s = (beg < end) ? __ldg(&g_csr[beg]) : 0;
        for (int j = beg; j < end; j++) {
            float as = __ldg(&g_asrc[s * 4 + head]);
            uint2 raw = *(const uint2*)&g_h[(long long)s * 128 + lane * 4];
            int s_next = (j + 1 < end) ? __ldg(&g_csr[j + 1]) : 0;

            float l = as + adv;
            l = fmaxf(l, 0.2f * l);
            float e = __expf(l);
            den += e;

            __half2 h01 = *(__half2*)&raw.x;
            __half2 h23 = *(__half2*)&raw.y;
            float2 f01 = __half22float2(h01);
            float2 f23 = __half22float2(h23);
            ax += f01.x * e;
            ay += f01.y * e;
            az += f23.x * e;
            aw += f23.y * e;
            s = s_next;
        }

        float inv = __fdividef(1.0f, den);
        float4 bv = *(const float4*)&bias[lane * 4];
        float4 ov;
        ov.x = fast_tanh(ax * inv + bv.x);
        ov.y = fast_tanh(ay * inv + bv.y);
        ov.z = fast_tanh(az * inv + bv.z);
        ov.w = fast_tanh(aw * inv + bv.w);
        *(float4*)&out[(long long)d * 128 + lane * 4] = ov;
    }

    __syncthreads();
    if (threadIdx.x == 0) {
        int c = atomicAdd(&g_agg_done, 1);
        if (c == n_agg_blocks - 1) {
            g_agg_done = 0;
            g_gemm_done = 0;
            g_bar = 0u;
            __threadfence();
        }
    }
}

// ---------------------------------------------------------------------------
// Host-side one-time setup: side stream + events.
// ---------------------------------------------------------------------------
static cudaStream_t g_s1 = 0;
static cudaEvent_t  g_e0 = 0, g_e1 = 0;
static bool g_forked = false;
static struct SideStreamInit {
    SideStreamInit() {
        bool ok = true;
        ok &= (cudaStreamCreateWithFlags(&g_s1, cudaStreamNonBlocking) == cudaSuccess);
        ok &= (cudaEventCreateWithFlags(&g_e0, cudaEventDisableTiming) == cudaSuccess);
        ok &= (cudaEventCreateWithFlags(&g_e1, cudaEventDisableTiming) == cudaSuccess);
        g_forked = ok;
    }
} g_side_stream_init;

// ---------------------------------------------------------------------------
extern "C" void kernel_launch(void* const* d_in, const int* in_sizes, int n_in,
                              void* d_out, int out_size) {
    const float* x     = (const float*)d_in[0];
    const void*  ei    = d_in[1];
    const float* W     = (const float*)d_in[2];
    const float* att_s = (const float*)d_in[3];
    const float* att_d = (const float*)d_in[4];
    const float* bias  = (const float*)d_in[5];
    float* out = (float*)d_out;

    int N = in_sizes[0] / 128;
    int E = in_sizes[1] / 2;
    int ngemm = (N + 63) / 64;
    int nagg  = (N * 32 + 127) / 128;

    if (g_forked) {
        cudaEventRecord(g_e0, 0);
        cudaStreamWaitEvent(g_s1, g_e0, 0);
        wconv_kernel<<<(8 * 16 * 32 + 127) / 128, 128, 0, g_s1>>>(W);
        gemm_mma_kernel<<<ngemm, 128, 0, g_s1>>>(x, att_s, att_d, N);
        cudaEventRecord(g_e1, g_s1);

        build_kernel<<<BGRID, BTHREADS>>>(ei, E, N);
        agg_kernel<<<nagg, 128>>>(out, bias, N, ngemm, nagg);

        cudaStreamWaitEvent(0, g_e1, 0);   // closes capture; off critical path
    } else {
        wconv_kernel<<<(8 * 16 * 32 + 127) / 128, 128>>>(W);
        gemm_mma_kernel<<<ngemm, 128>>>(x, att_s, att_d, N);
        build_kernel<<<BGRID, BTHREADS>>>(ei, E, N);
        agg_kernel<<<nagg, 128>>>(out, bias, N, ngemm, nagg);
    }
}